// round 7
// baseline (speedup 1.0000x reference)
#include <cuda_runtime.h>
#include <cuda_bf16.h>
#include <cuda_fp16.h>
#include <math.h>
#include <stdint.h>

#define NB   4
#define C3   256
#define HW3  3136
#define HWP3 3200
#define C4   512
#define HW4  784
#define HWP4 896
#define EPSV 1e-5f
#define LOG2E 1.4426950408889634f
#define K2C   2.8853900817779268f   /* 2*log2(e) */

#define RPSS  16    /* rows per slice, colsum */
#define NSLS3 196   /* 3136/16 */
#define NSLS4 49    /* 784/16 */

// ---------------- scratch ----------------
__device__ __nv_bfloat16 d_tT3[(size_t)NB * HWP3 * C3];
__device__ __nv_bfloat16 d_gT3[(size_t)NB * HWP3 * C3];
__device__ __nv_bfloat16 d_tT4[(size_t)NB * HWP4 * C4];
__device__ __nv_bfloat16 d_gT4[(size_t)NB * HWP4 * C4];
__device__ __half d_cd3[(size_t)NB * HW3 * HW3];
__device__ __half d_cd4[(size_t)NB * HW4 * HW4];
__device__ float d_mean[NB * HW3], d_rg[NB * HW3], d_rt[NB * HW3];
__device__ unsigned int d_dmin[NB * HW3];   // orderable-uint column min
__device__ float d_S[NB * HW3];             // column sum of exp2 terms
__device__ float d_rm3[NB * HW3], d_rm4[NB * HW4];

// ---------------- helpers --------------------------------------------------------
__device__ __forceinline__ unsigned int fl2u(float f) {
    unsigned int u = __float_as_uint(f);
    return (u & 0x80000000u) ? ~u : (u | 0x80000000u);
}
__device__ __forceinline__ float u2fl(unsigned int u) {
    unsigned int v = (u & 0x80000000u) ? (u & 0x7FFFFFFFu) : ~u;
    return __uint_as_float(v);
}
__device__ __forceinline__ uint32_t smem_u32(const void* p) {
    uint32_t a;
    asm("{ .reg .u64 t; cvta.to.shared.u64 t, %1; cvt.u32.u64 %0, t; }" : "=r"(a) : "l"(p));
    return a;
}
__device__ __forceinline__ void cp16(uint32_t dst, const void* src) {
    asm volatile("cp.async.cg.shared.global [%0], [%1], 16;" :: "r"(dst), "l"(src));
}
#define CP_COMMIT() asm volatile("cp.async.commit_group;" ::: "memory")
#define CP_WAITG1() asm volatile("cp.async.wait_group 1;" ::: "memory")

__device__ __forceinline__ void ldm_x4(uint32_t* r, uint32_t addr) {
    asm volatile("ldmatrix.sync.aligned.m8n8.x4.shared.b16 {%0,%1,%2,%3}, [%4];"
        : "=r"(r[0]), "=r"(r[1]), "=r"(r[2]), "=r"(r[3]) : "r"(addr));
}
__device__ __forceinline__ void mma_bf16(float* d, const uint32_t* a, const uint32_t* b) {
    asm volatile(
        "mma.sync.aligned.m16n8k16.row.col.f32.bf16.bf16.f32 "
        "{%0,%1,%2,%3}, {%4,%5,%6,%7}, {%8,%9}, {%0,%1,%2,%3};"
        : "+f"(d[0]), "+f"(d[1]), "+f"(d[2]), "+f"(d[3])
        : "r"(a[0]), "r"(a[1]), "r"(a[2]), "r"(a[3]), "r"(b[0]), "r"(b[1]));
}

// ---------------- 1) stats + init dmin/S -----------------------------------------
__global__ __launch_bounds__(128) void stats_k(
    const float* __restrict__ g, const float* __restrict__ t,
    float* __restrict__ mean, float* __restrict__ rg, float* __restrict__ rt,
    unsigned int* __restrict__ dmin, float* __restrict__ S,
    int C, int HW)
{
    int n = blockIdx.y, lane = threadIdx.x & 31, cp = threadIdx.x >> 5;
    int hw = blockIdx.x * 32 + lane;
    bool ok = hw < HW;
    __shared__ float red[4][4][32];
    const float* gp = g + (size_t)n * C * HW + hw;
    const float* tp = t + (size_t)n * C * HW + hw;
    float st = 0, st2 = 0, sg = 0, sg2 = 0;
    if (ok) {
        #pragma unroll 4
        for (int c = cp; c < C; c += 4) {
            float tv = tp[(size_t)c * HW], gv = gp[(size_t)c * HW];
            st += tv; st2 += tv * tv; sg += gv; sg2 += gv * gv;
        }
    }
    red[0][cp][lane] = st; red[1][cp][lane] = st2;
    red[2][cp][lane] = sg; red[3][cp][lane] = sg2;
    __syncthreads();
    if (cp == 0 && ok) {
        st  = red[0][0][lane] + red[0][1][lane] + red[0][2][lane] + red[0][3][lane];
        st2 = red[1][0][lane] + red[1][1][lane] + red[1][2][lane] + red[1][3][lane];
        sg  = red[2][0][lane] + red[2][1][lane] + red[2][2][lane] + red[2][3][lane];
        sg2 = red[3][0][lane] + red[3][1][lane] + red[3][2][lane] + red[3][3][lane];
        float mu = st / (float)C;
        mean[n * HW + hw] = mu;
        rt[n * HW + hw] = rsqrtf(st2 - (float)C * mu * mu);
        rg[n * HW + hw] = rsqrtf(sg2 - 2.f * mu * sg + (float)C * mu * mu);
        dmin[n * HW + hw] = 0xFFFFFFFFu;
        S[n * HW + hw] = 0.f;
    }
}

// ---------------- 2) transpose+normalize+bf16 ------------------------------------
__global__ __launch_bounds__(256) void trans_k(
    const float* __restrict__ g, const float* __restrict__ t,
    const float* __restrict__ mean, const float* __restrict__ rg, const float* __restrict__ rt,
    __nv_bfloat16* __restrict__ gT, __nv_bfloat16* __restrict__ tT,
    int C, int HW, int HWpad)
{
    __shared__ float sg[32][33], st[32][33];
    int n = blockIdx.z;
    int c0 = blockIdx.x * 32, hw0 = blockIdx.y * 32;
    int tx = threadIdx.x & 31, ty = threadIdx.x >> 5;
    int hw = hw0 + tx;
    float mu = 0.f, sgn = 0.f, stn = 0.f;
    if (hw < HW) {
        mu  = mean[n * HW + hw];
        sgn = rg[n * HW + hw];
        stn = rt[n * HW + hw];
    }
    const size_t ib = (size_t)n * C * HW;
    #pragma unroll
    for (int i = 0; i < 4; i++) {
        int c = c0 + ty + i * 8;
        float vg = 0.f, vt = 0.f;
        if (hw < HW) {
            vg = (g[ib + (size_t)c * HW + hw] - mu) * sgn;
            vt = (t[ib + (size_t)c * HW + hw] - mu) * stn;
        }
        sg[ty + i * 8][tx] = vg;
        st[ty + i * 8][tx] = vt;
    }
    __syncthreads();
    #pragma unroll
    for (int i = 0; i < 4; i++) {
        int hwo = hw0 + ty + i * 8;
        int c = c0 + tx;
        size_t o = ((size_t)n * HWpad + hwo) * C + c;
        gT[o] = __float2bfloat16(sg[tx][ty + i * 8]);
        tT[o] = __float2bfloat16(st[tx][ty + i * 8]);
    }
}

// ---------------- 3) mma.sync bf16 GEMM + fused column-min (atomicMin) -----------
// CTA 128x128, 8 warps (4m x 2n), K chunks of 64, 3-stage cp.async, single sync
// per chunk, 2 CTAs/SM.
#define KCH    64
#define RSTR   144
#define ABUF   18432              /* 128 * 144 */
#define STG    3
#define SMEMT  (STG * 2 * ABUF)   /* 110592 */

__global__ __launch_bounds__(256, 2) void gemm_cd_mma(
    const __nv_bfloat16* __restrict__ A, const __nv_bfloat16* __restrict__ B,
    __half* __restrict__ CD, unsigned int* __restrict__ dmin,
    int C, int P, int Q, int Mpad, int Npad)
{
    extern __shared__ char dsm[];
    const int tid  = threadIdx.x;
    const int lane = tid & 31;
    const int wid  = tid >> 5;
    const int wm   = wid & 3;
    const int wn   = wid >> 2;
    const int n    = blockIdx.z;
    const int m0   = blockIdx.y * 128;
    const int n0   = blockIdx.x * 128;

    const uint32_t sbase = smem_u32(dsm);
    const uint32_t sA = sbase;
    const uint32_t sB = sbase + STG * ABUF;

    const __nv_bfloat16* An = A + ((size_t)n * Mpad + m0) * C;
    const __nv_bfloat16* Bn = B + ((size_t)n * Npad + n0) * C;

    const int row_ld = tid >> 3;
    const int c16    = tid & 7;

    float acc[2][8][4];
    #pragma unroll
    for (int mi = 0; mi < 2; mi++)
        #pragma unroll
        for (int ni = 0; ni < 8; ni++)
            #pragma unroll
            for (int e = 0; e < 4; e++) acc[mi][ni][e] = 0.f;

    const int nch = C >> 6;

    auto load_chunk = [&](int c, int buf) {
        const __nv_bfloat16* Ak = An + c * KCH;
        const __nv_bfloat16* Bk = Bn + c * KCH;
        uint32_t da = sA + buf * ABUF + row_ld * RSTR + c16 * 16;
        uint32_t db = sB + buf * ABUF + row_ld * RSTR + c16 * 16;
        #pragma unroll
        for (int i = 0; i < 4; i++) {
            int r = row_ld + i * 32;
            cp16(da + i * 32 * RSTR, Ak + (size_t)r * C + c16 * 8);
            cp16(db + i * 32 * RSTR, Bk + (size_t)r * C + c16 * 8);
        }
    };

    // prologue: chunks 0,1 -> bufs 0,1 (one commit each)
    load_chunk(0, 0);
    CP_COMMIT();
    if (nch > 1) load_chunk(1, 1);
    CP_COMMIT();

    const uint32_t aRow  = (uint32_t)(wm * 32 + (lane & 15));
    const uint32_t aColH = (uint32_t)((lane >> 4) * 8);
    const int quad = lane >> 3, r8 = lane & 7;
    const uint32_t bRow  = (uint32_t)(wn * 64 + (quad >> 1) * 8 + r8);
    const uint32_t bColH = (uint32_t)((quad & 1) * 8);

    int buf = 0, ldbuf = 2;
    for (int c = 0; c < nch; c++) {
        CP_WAITG1();                 // chunk c resident
        __syncthreads();             // all warps past chunk c-1 compute
        const int pf = c + STG - 1;
        if (pf < nch) {
            load_chunk(pf, ldbuf);
            ldbuf = (ldbuf == STG - 1) ? 0 : ldbuf + 1;
        }
        CP_COMMIT();                 // always commit (empty groups OK)

        const uint32_t bA = sA + buf * ABUF;
        const uint32_t bB = sB + buf * ABUF;

        #pragma unroll
        for (int ks = 0; ks < 4; ks++) {
            const int k0 = ks * 16;
            uint32_t af[2][4];
            #pragma unroll
            for (int mi = 0; mi < 2; mi++)
                ldm_x4(af[mi], bA + (aRow + mi * 16) * RSTR + (k0 + aColH) * 2);
            uint32_t bfr[4][4];
            #pragma unroll
            for (int nb = 0; nb < 4; nb++)
                ldm_x4(bfr[nb], bB + (bRow + nb * 16) * RSTR + (k0 + bColH) * 2);
            #pragma unroll
            for (int mi = 0; mi < 2; mi++) {
                #pragma unroll
                for (int nb = 0; nb < 4; nb++) {
                    mma_bf16(acc[mi][nb * 2],     af[mi], &bfr[nb][0]);
                    mma_bf16(acc[mi][nb * 2 + 1], af[mi], &bfr[nb][2]);
                }
            }
        }
        buf = (buf == STG - 1) ? 0 : buf + 1;
    }

    // ---- epilogue: cd = (1-acc)/2 -> fp16 store + per-CTA column min ----
    const int gid = lane >> 2, t4 = lane & 3;
    float cmin[16];
    #pragma unroll
    for (int i = 0; i < 16; i++) cmin[i] = INFINITY;
    __half* Cn = CD + (size_t)n * P * Q;
    #pragma unroll
    for (int mi = 0; mi < 2; mi++) {
        #pragma unroll
        for (int h = 0; h < 2; h++) {
            int r = m0 + wm * 32 + mi * 16 + h * 8 + gid;
            if (r < P) {
                __half* rp = Cn + (size_t)r * Q;
                #pragma unroll
                for (int ni = 0; ni < 8; ni++) {
                    int col = n0 + wn * 64 + ni * 8 + t4 * 2;
                    float fa = 0.5f * (1.0f - acc[mi][ni][h * 2]);
                    float fb = 0.5f * (1.0f - acc[mi][ni][h * 2 + 1]);
                    cmin[ni * 2]     = fminf(cmin[ni * 2], fa);
                    cmin[ni * 2 + 1] = fminf(cmin[ni * 2 + 1], fb);
                    if (col < Q)
                        *(__half2*)(rp + col) = __floats2half2_rn(fa, fb);
                }
            }
        }
    }
    #pragma unroll
    for (int o = 4; o < 32; o <<= 1)
        #pragma unroll
        for (int i = 0; i < 16; i++)
            cmin[i] = fminf(cmin[i], __shfl_xor_sync(0xffffffffu, cmin[i], o));

    __syncthreads();                 // mainloop smem reads done before reuse
    float* smin = (float*)dsm;
    if (gid == 0) {
        #pragma unroll
        for (int ni = 0; ni < 8; ni++) {
            smin[wm * 128 + wn * 64 + ni * 8 + t4 * 2]     = cmin[ni * 2];
            smin[wm * 128 + wn * 64 + ni * 8 + t4 * 2 + 1] = cmin[ni * 2 + 1];
        }
    }
    __syncthreads();
    if (tid < 128) {
        int colg = n0 + tid;
        if (colg < Q) {
            float m = fminf(fminf(smin[tid], smin[128 + tid]),
                            fminf(smin[256 + tid], smin[384 + tid]));
            atomicMin(&dmin[n * Q + colg], fl2u(m));
        }
    }
}

// ---------------- 4) column sum of exp2(c0e*cd + 2log2e): atomicAdd to S ---------
__global__ __launch_bounds__(256) void colsum_k(
    const __half* __restrict__ cd, const unsigned int* __restrict__ dmin,
    float* __restrict__ S, int P, int Q, int rps)
{
    int n = blockIdx.z, sl = blockIdx.y;
    int nq8 = Q >> 3;
    int q8 = blockIdx.x * 256 + threadIdx.x;
    if (q8 >= nq8) return;
    const uint4* base = (const uint4*)(cd + (size_t)n * P * Q) + q8;

    // inline c0e from global column min
    float ce[8];
    {
        uint4 u0 = *(const uint4*)(dmin + n * Q + q8 * 8);
        uint4 u1 = *(const uint4*)(dmin + n * Q + q8 * 8 + 4);
        ce[0] = (-2.0f * LOG2E) / (u2fl(u0.x) + EPSV);
        ce[1] = (-2.0f * LOG2E) / (u2fl(u0.y) + EPSV);
        ce[2] = (-2.0f * LOG2E) / (u2fl(u0.z) + EPSV);
        ce[3] = (-2.0f * LOG2E) / (u2fl(u0.w) + EPSV);
        ce[4] = (-2.0f * LOG2E) / (u2fl(u1.x) + EPSV);
        ce[5] = (-2.0f * LOG2E) / (u2fl(u1.y) + EPSV);
        ce[6] = (-2.0f * LOG2E) / (u2fl(u1.z) + EPSV);
        ce[7] = (-2.0f * LOG2E) / (u2fl(u1.w) + EPSV);
    }
    int r0 = sl * rps;
    float s[8];
    #pragma unroll
    for (int i = 0; i < 8; i++) s[i] = 0.f;
    #pragma unroll 4
    for (int r = r0; r < r0 + rps; r++) {
        uint4 v = base[(size_t)r * nq8];
        float2 f0 = __half22float2(*(__half2*)&v.x);
        float2 f1 = __half22float2(*(__half2*)&v.y);
        float2 f2 = __half22float2(*(__half2*)&v.z);
        float2 f3 = __half22float2(*(__half2*)&v.w);
        s[0] += exp2f(fmaf(ce[0], f0.x, K2C));
        s[1] += exp2f(fmaf(ce[1], f0.y, K2C));
        s[2] += exp2f(fmaf(ce[2], f1.x, K2C));
        s[3] += exp2f(fmaf(ce[3], f1.y, K2C));
        s[4] += exp2f(fmaf(ce[4], f2.x, K2C));
        s[5] += exp2f(fmaf(ce[5], f2.y, K2C));
        s[6] += exp2f(fmaf(ce[6], f3.x, K2C));
        s[7] += exp2f(fmaf(ce[7], f3.y, K2C));
    }
    float* Sp = S + n * Q + q8 * 8;
    #pragma unroll
    for (int i = 0; i < 8; i++) atomicAdd(Sp + i, s[i]);
}

// ---------------- 5) row max: rm_p = max_q (c0e_q*cd + be_q) ---------------------
__global__ __launch_bounds__(256) void rowmax_k(
    const __half* __restrict__ cd, const unsigned int* __restrict__ dmin,
    const float* __restrict__ S, float* __restrict__ rm, int P, int Q)
{
    __shared__ float sc[HW3], sb[HW3];
    int n = blockIdx.y;
    for (int i = threadIdx.x; i < Q; i += 256) {
        sc[i] = (-2.0f * LOG2E) / (u2fl(dmin[n * Q + i]) + EPSV);
        sb[i] = K2C - log2f(S[n * Q + i]);
    }
    __syncthreads();
    int p = blockIdx.x * 8 + (threadIdx.x >> 5);
    int lane = threadIdx.x & 31;
    if (p >= P) return;
    const uint4* row = (const uint4*)(cd + (size_t)n * P * Q + (size_t)p * Q);
    int nq8 = Q >> 3;
    float m = -3.4e38f;
    for (int i = lane; i < nq8; i += 32) {
        uint4 v = row[i];
        int qb = i * 8;
        float2 f0 = __half22float2(*(__half2*)&v.x);
        float2 f1 = __half22float2(*(__half2*)&v.y);
        float2 f2 = __half22float2(*(__half2*)&v.z);
        float2 f3 = __half22float2(*(__half2*)&v.w);
        m = fmaxf(m, fmaf(sc[qb],     f0.x, sb[qb]));
        m = fmaxf(m, fmaf(sc[qb + 1], f0.y, sb[qb + 1]));
        m = fmaxf(m, fmaf(sc[qb + 2], f1.x, sb[qb + 2]));
        m = fmaxf(m, fmaf(sc[qb + 3], f1.y, sb[qb + 3]));
        m = fmaxf(m, fmaf(sc[qb + 4], f2.x, sb[qb + 4]));
        m = fmaxf(m, fmaf(sc[qb + 5], f2.y, sb[qb + 5]));
        m = fmaxf(m, fmaf(sc[qb + 6], f3.x, sb[qb + 6]));
        m = fmaxf(m, fmaf(sc[qb + 7], f3.y, sb[qb + 7]));
    }
    #pragma unroll
    for (int o = 16; o > 0; o >>= 1)
        m = fmaxf(m, __shfl_xor_sync(0xffffffffu, m, o));
    if (lane == 0) rm[n * P + p] = m;
}

// ---------------- 6) final -------------------------------------------------------
__global__ __launch_bounds__(256) void final_k(
    const float* __restrict__ rm3, const float* __restrict__ rm4,
    float* __restrict__ out)
{
    __shared__ float red[256];
    int tid = threadIdx.x;
    float total = 0.f;
    for (int n = 0; n < NB; n++) {
        float s = 0.f;
        for (int p = tid; p < HW3; p += 256) s += exp2f(rm3[n * HW3 + p]);
        red[tid] = s;
        __syncthreads();
        for (int o = 128; o > 0; o >>= 1) {
            if (tid < o) red[tid] += red[tid + o];
            __syncthreads();
        }
        total += 0.5f * (-logf(red[0] / (float)HW3));
        __syncthreads();
    }
    for (int n = 0; n < NB; n++) {
        float s = 0.f;
        for (int p = tid; p < HW4; p += 256) s += exp2f(rm4[n * HW4 + p]);
        red[tid] = s;
        __syncthreads();
        for (int o = 128; o > 0; o >>= 1) {
            if (tid < o) red[tid] += red[tid + o];
            __syncthreads();
        }
        total += 1.0f * (-logf(red[0] / (float)HW4));
        __syncthreads();
    }
    if (tid == 0) out[0] = total;
}

// ---------------- launch ---------------------------------------------------------
extern "C" void kernel_launch(void* const* d_in, const int* in_sizes, int n_in,
                              void* d_out, int out_size)
{
    const float* gen3 = (const float*)d_in[0];
    const float* tar3 = (const float*)d_in[1];
    const float* gen4 = (const float*)d_in[2];
    const float* tar4 = (const float*)d_in[3];

    __nv_bfloat16 *tT3, *gT3, *tT4, *gT4;
    __half *cd3, *cd4;
    float *mean, *rg, *rt, *S, *rm3, *rm4;
    unsigned int* dmin;
    cudaGetSymbolAddress((void**)&tT3, d_tT3);
    cudaGetSymbolAddress((void**)&gT3, d_gT3);
    cudaGetSymbolAddress((void**)&tT4, d_tT4);
    cudaGetSymbolAddress((void**)&gT4, d_gT4);
    cudaGetSymbolAddress((void**)&cd3, d_cd3);
    cudaGetSymbolAddress((void**)&cd4, d_cd4);
    cudaGetSymbolAddress((void**)&mean, d_mean);
    cudaGetSymbolAddress((void**)&rg, d_rg);
    cudaGetSymbolAddress((void**)&rt, d_rt);
    cudaGetSymbolAddress((void**)&dmin, d_dmin);
    cudaGetSymbolAddress((void**)&S, d_S);
    cudaGetSymbolAddress((void**)&rm3, d_rm3);
    cudaGetSymbolAddress((void**)&rm4, d_rm4);

    cudaFuncSetAttribute(gemm_cd_mma, cudaFuncAttributeMaxDynamicSharedMemorySize, SMEMT);

    // ---- layer 3 ----
    stats_k<<<dim3(HW3 / 32, NB), 128>>>(gen3, tar3, mean, rg, rt, dmin, S, C3, HW3);
    trans_k<<<dim3(C3 / 32, HWP3 / 32, NB), 256>>>(gen3, tar3, mean, rg, rt, gT3, tT3, C3, HW3, HWP3);
    gemm_cd_mma<<<dim3(HWP3 / 128, HWP3 / 128, NB), 256, SMEMT>>>(
        tT3, gT3, cd3, dmin, C3, HW3, HW3, HWP3, HWP3);
    colsum_k<<<dim3(2, NSLS3, NB), 256>>>(cd3, dmin, S, HW3, HW3, RPSS);
    rowmax_k<<<dim3((HW3 + 7) / 8, NB), 256>>>(cd3, dmin, S, rm3, HW3, HW3);

    // ---- layer 4 ----
    stats_k<<<dim3((HW4 + 31) / 32, NB), 128>>>(gen4, tar4, mean, rg, rt, dmin, S, C4, HW4);
    trans_k<<<dim3(C4 / 32, HWP4 / 32, NB), 256>>>(gen4, tar4, mean, rg, rt, gT4, tT4, C4, HW4, HWP4);
    gemm_cd_mma<<<dim3(HWP4 / 128, HWP4 / 128, NB), 256, SMEMT>>>(
        tT4, gT4, cd4, dmin, C4, HW4, HW4, HWP4, HWP4);
    colsum_k<<<dim3(1, NSLS4, NB), 256>>>(cd4, dmin, S, HW4, HW4, RPSS);
    rowmax_k<<<dim3((HW4 + 7) / 8, NB), 256>>>(cd4, dmin, S, rm4, HW4, HW4);

    final_k<<<1, 256>>>(rm3, rm4, (float*)d_out);
}

// round 8
// speedup vs baseline: 1.0786x; 1.0786x over previous
#include <cuda_runtime.h>
#include <cuda_bf16.h>
#include <cuda_fp16.h>
#include <math.h>
#include <stdint.h>

#define NB   4
#define C3   256
#define HW3  3136
#define HWP3 3200
#define C4   512
#define HW4  784
#define HWP4 896
#define EPSV 1e-5f
#define LOG2E 1.4426950408889634f
#define K2C   2.8853900817779268f   /* 2*log2(e) */

#define RPSS  16    /* rows per slice, colsum */
#define NSLS3 196   /* 3136/16 */
#define NSLS4 49    /* 784/16 */

// ---------------- scratch ----------------
__device__ __nv_bfloat16 d_tT3[(size_t)NB * HWP3 * C3];
__device__ __nv_bfloat16 d_gT3[(size_t)NB * HWP3 * C3];
__device__ __nv_bfloat16 d_tT4[(size_t)NB * HWP4 * C4];
__device__ __nv_bfloat16 d_gT4[(size_t)NB * HWP4 * C4];
__device__ __half d_cd3[(size_t)NB * HW3 * HW3];
__device__ __half d_cd4[(size_t)NB * HW4 * HW4];
__device__ float d_mean[NB * HW3], d_rg[NB * HW3], d_rt[NB * HW3];
__device__ unsigned int d_dmin[NB * HW3];            // orderable-uint column min
__device__ float d_pred[(size_t)NB * NSLS3 * HW3];   // colsum partials
__device__ float d_be[NB * HW3];
__device__ float d_rm3[NB * HW3], d_rm4[NB * HW4];

// ---------------- helpers --------------------------------------------------------
__device__ __forceinline__ unsigned int fl2u(float f) {
    unsigned int u = __float_as_uint(f);
    return (u & 0x80000000u) ? ~u : (u | 0x80000000u);
}
__device__ __forceinline__ float u2fl(unsigned int u) {
    unsigned int v = (u & 0x80000000u) ? (u & 0x7FFFFFFFu) : ~u;
    return __uint_as_float(v);
}
__device__ __forceinline__ uint32_t smem_u32(const void* p) {
    uint32_t a;
    asm("{ .reg .u64 t; cvta.to.shared.u64 t, %1; cvt.u32.u64 %0, t; }" : "=r"(a) : "l"(p));
    return a;
}
__device__ __forceinline__ void cp16(uint32_t dst, const void* src) {
    asm volatile("cp.async.cg.shared.global [%0], [%1], 16;" :: "r"(dst), "l"(src));
}
#define CP_COMMIT() asm volatile("cp.async.commit_group;" ::: "memory")
#define CP_WAITG1() asm volatile("cp.async.wait_group 1;" ::: "memory")

__device__ __forceinline__ void ldm_x4(uint32_t* r, uint32_t addr) {
    asm volatile("ldmatrix.sync.aligned.m8n8.x4.shared.b16 {%0,%1,%2,%3}, [%4];"
        : "=r"(r[0]), "=r"(r[1]), "=r"(r[2]), "=r"(r[3]) : "r"(addr));
}
__device__ __forceinline__ void mma_bf16(float* d, const uint32_t* a, const uint32_t* b) {
    asm volatile(
        "mma.sync.aligned.m16n8k16.row.col.f32.bf16.bf16.f32 "
        "{%0,%1,%2,%3}, {%4,%5,%6,%7}, {%8,%9}, {%0,%1,%2,%3};"
        : "+f"(d[0]), "+f"(d[1]), "+f"(d[2]), "+f"(d[3])
        : "r"(a[0]), "r"(a[1]), "r"(a[2]), "r"(a[3]), "r"(b[0]), "r"(b[1]));
}

// ---------------- 1) stats + init dmin -------------------------------------------
__global__ __launch_bounds__(128) void stats_k(
    const float* __restrict__ g, const float* __restrict__ t,
    float* __restrict__ mean, float* __restrict__ rg, float* __restrict__ rt,
    unsigned int* __restrict__ dmin,
    int C, int HW)
{
    int n = blockIdx.y, lane = threadIdx.x & 31, cp = threadIdx.x >> 5;
    int hw = blockIdx.x * 32 + lane;
    bool ok = hw < HW;
    __shared__ float red[4][4][32];
    const float* gp = g + (size_t)n * C * HW + hw;
    const float* tp = t + (size_t)n * C * HW + hw;
    float st = 0, st2 = 0, sg = 0, sg2 = 0;
    if (ok) {
        #pragma unroll 4
        for (int c = cp; c < C; c += 4) {
            float tv = tp[(size_t)c * HW], gv = gp[(size_t)c * HW];
            st += tv; st2 += tv * tv; sg += gv; sg2 += gv * gv;
        }
    }
    red[0][cp][lane] = st; red[1][cp][lane] = st2;
    red[2][cp][lane] = sg; red[3][cp][lane] = sg2;
    __syncthreads();
    if (cp == 0 && ok) {
        st  = red[0][0][lane] + red[0][1][lane] + red[0][2][lane] + red[0][3][lane];
        st2 = red[1][0][lane] + red[1][1][lane] + red[1][2][lane] + red[1][3][lane];
        sg  = red[2][0][lane] + red[2][1][lane] + red[2][2][lane] + red[2][3][lane];
        sg2 = red[3][0][lane] + red[3][1][lane] + red[3][2][lane] + red[3][3][lane];
        float mu = st / (float)C;
        mean[n * HW + hw] = mu;
        rt[n * HW + hw] = rsqrtf(st2 - (float)C * mu * mu);
        rg[n * HW + hw] = rsqrtf(sg2 - 2.f * mu * sg + (float)C * mu * mu);
        dmin[n * HW + hw] = 0xFFFFFFFFu;
    }
}

// ---------------- 2) transpose+normalize+bf16 ------------------------------------
__global__ __launch_bounds__(256) void trans_k(
    const float* __restrict__ g, const float* __restrict__ t,
    const float* __restrict__ mean, const float* __restrict__ rg, const float* __restrict__ rt,
    __nv_bfloat16* __restrict__ gT, __nv_bfloat16* __restrict__ tT,
    int C, int HW, int HWpad)
{
    __shared__ float sg[32][33], st[32][33];
    int n = blockIdx.z;
    int c0 = blockIdx.x * 32, hw0 = blockIdx.y * 32;
    int tx = threadIdx.x & 31, ty = threadIdx.x >> 5;
    int hw = hw0 + tx;
    float mu = 0.f, sgn = 0.f, stn = 0.f;
    if (hw < HW) {
        mu  = mean[n * HW + hw];
        sgn = rg[n * HW + hw];
        stn = rt[n * HW + hw];
    }
    const size_t ib = (size_t)n * C * HW;
    #pragma unroll
    for (int i = 0; i < 4; i++) {
        int c = c0 + ty + i * 8;
        float vg = 0.f, vt = 0.f;
        if (hw < HW) {
            vg = (g[ib + (size_t)c * HW + hw] - mu) * sgn;
            vt = (t[ib + (size_t)c * HW + hw] - mu) * stn;
        }
        sg[ty + i * 8][tx] = vg;
        st[ty + i * 8][tx] = vt;
    }
    __syncthreads();
    #pragma unroll
    for (int i = 0; i < 4; i++) {
        int hwo = hw0 + ty + i * 8;
        int c = c0 + tx;
        size_t o = ((size_t)n * HWpad + hwo) * C + c;
        gT[o] = __float2bfloat16(sg[tx][ty + i * 8]);
        tT[o] = __float2bfloat16(st[tx][ty + i * 8]);
    }
}

// ---------------- 3) mma.sync bf16 GEMM + fused column-min (atomicMin) -----------
#define KCH    64
#define RSTR   144
#define ABUF   18432              /* 128 * 144 */
#define STG    3
#define SMEMT  (STG * 2 * ABUF)   /* 110592 */

__global__ __launch_bounds__(256, 2) void gemm_cd_mma(
    const __nv_bfloat16* __restrict__ A, const __nv_bfloat16* __restrict__ B,
    __half* __restrict__ CD, unsigned int* __restrict__ dmin,
    int C, int P, int Q, int Mpad, int Npad)
{
    extern __shared__ char dsm[];
    const int tid  = threadIdx.x;
    const int lane = tid & 31;
    const int wid  = tid >> 5;
    const int wm   = wid & 3;
    const int wn   = wid >> 2;
    const int n    = blockIdx.z;
    const int m0   = blockIdx.y * 128;
    const int n0   = blockIdx.x * 128;

    const uint32_t sbase = smem_u32(dsm);
    const uint32_t sA = sbase;
    const uint32_t sB = sbase + STG * ABUF;

    const __nv_bfloat16* An = A + ((size_t)n * Mpad + m0) * C;
    const __nv_bfloat16* Bn = B + ((size_t)n * Npad + n0) * C;

    const int row_ld = tid >> 3;
    const int c16    = tid & 7;

    float acc[2][8][4];
    #pragma unroll
    for (int mi = 0; mi < 2; mi++)
        #pragma unroll
        for (int ni = 0; ni < 8; ni++)
            #pragma unroll
            for (int e = 0; e < 4; e++) acc[mi][ni][e] = 0.f;

    const int nch = C >> 6;

    auto load_chunk = [&](int c, int buf) {
        const __nv_bfloat16* Ak = An + c * KCH;
        const __nv_bfloat16* Bk = Bn + c * KCH;
        uint32_t da = sA + buf * ABUF + row_ld * RSTR + c16 * 16;
        uint32_t db = sB + buf * ABUF + row_ld * RSTR + c16 * 16;
        #pragma unroll
        for (int i = 0; i < 4; i++) {
            int r = row_ld + i * 32;
            cp16(da + i * 32 * RSTR, Ak + (size_t)r * C + c16 * 8);
            cp16(db + i * 32 * RSTR, Bk + (size_t)r * C + c16 * 8);
        }
    };

    load_chunk(0, 0);
    CP_COMMIT();
    if (nch > 1) load_chunk(1, 1);
    CP_COMMIT();

    const uint32_t aRow  = (uint32_t)(wm * 32 + (lane & 15));
    const uint32_t aColH = (uint32_t)((lane >> 4) * 8);
    const int quad = lane >> 3, r8 = lane & 7;
    const uint32_t bRow  = (uint32_t)(wn * 64 + (quad >> 1) * 8 + r8);
    const uint32_t bColH = (uint32_t)((quad & 1) * 8);

    int buf = 0, ldbuf = 2;
    for (int c = 0; c < nch; c++) {
        CP_WAITG1();
        __syncthreads();
        const int pf = c + STG - 1;
        if (pf < nch) {
            load_chunk(pf, ldbuf);
            ldbuf = (ldbuf == STG - 1) ? 0 : ldbuf + 1;
        }
        CP_COMMIT();

        const uint32_t bA = sA + buf * ABUF;
        const uint32_t bB = sB + buf * ABUF;

        #pragma unroll
        for (int ks = 0; ks < 4; ks++) {
            const int k0 = ks * 16;
            uint32_t af[2][4];
            #pragma unroll
            for (int mi = 0; mi < 2; mi++)
                ldm_x4(af[mi], bA + (aRow + mi * 16) * RSTR + (k0 + aColH) * 2);
            uint32_t bfr[4][4];
            #pragma unroll
            for (int nb = 0; nb < 4; nb++)
                ldm_x4(bfr[nb], bB + (bRow + nb * 16) * RSTR + (k0 + bColH) * 2);
            #pragma unroll
            for (int mi = 0; mi < 2; mi++) {
                #pragma unroll
                for (int nb = 0; nb < 4; nb++) {
                    mma_bf16(acc[mi][nb * 2],     af[mi], &bfr[nb][0]);
                    mma_bf16(acc[mi][nb * 2 + 1], af[mi], &bfr[nb][2]);
                }
            }
        }
        buf = (buf == STG - 1) ? 0 : buf + 1;
    }

    // ---- epilogue: cd = (1-acc)/2 -> fp16 store + per-CTA column min ----
    const int gid = lane >> 2, t4 = lane & 3;
    float cmin[16];
    #pragma unroll
    for (int i = 0; i < 16; i++) cmin[i] = INFINITY;
    __half* Cn = CD + (size_t)n * P * Q;
    #pragma unroll
    for (int mi = 0; mi < 2; mi++) {
        #pragma unroll
        for (int h = 0; h < 2; h++) {
            int r = m0 + wm * 32 + mi * 16 + h * 8 + gid;
            if (r < P) {
                __half* rp = Cn + (size_t)r * Q;
                #pragma unroll
                for (int ni = 0; ni < 8; ni++) {
                    int col = n0 + wn * 64 + ni * 8 + t4 * 2;
                    float fa = 0.5f * (1.0f - acc[mi][ni][h * 2]);
                    float fb = 0.5f * (1.0f - acc[mi][ni][h * 2 + 1]);
                    cmin[ni * 2]     = fminf(cmin[ni * 2], fa);
                    cmin[ni * 2 + 1] = fminf(cmin[ni * 2 + 1], fb);
                    if (col < Q)
                        *(__half2*)(rp + col) = __floats2half2_rn(fa, fb);
                }
            }
        }
    }
    #pragma unroll
    for (int o = 4; o < 32; o <<= 1)
        #pragma unroll
        for (int i = 0; i < 16; i++)
            cmin[i] = fminf(cmin[i], __shfl_xor_sync(0xffffffffu, cmin[i], o));

    __syncthreads();
    float* smin = (float*)dsm;
    if (gid == 0) {
        #pragma unroll
        for (int ni = 0; ni < 8; ni++) {
            smin[wm * 128 + wn * 64 + ni * 8 + t4 * 2]     = cmin[ni * 2];
            smin[wm * 128 + wn * 64 + ni * 8 + t4 * 2 + 1] = cmin[ni * 2 + 1];
        }
    }
    __syncthreads();
    if (tid < 128) {
        int colg = n0 + tid;
        if (colg < Q) {
            float m = fminf(fminf(smin[tid], smin[128 + tid]),
                            fminf(smin[256 + tid], smin[384 + tid]));
            atomicMin(&dmin[n * Q + colg], fl2u(m));
        }
    }
}

// ---------------- 4) partial column sum of exp2(c0e*cd + 2log2e) -----------------
__global__ __launch_bounds__(256) void colsum_k(
    const __half* __restrict__ cd, const unsigned int* __restrict__ dmin,
    float* __restrict__ pout, int P, int Q, int rps, int nsl)
{
    int n = blockIdx.z, sl = blockIdx.y;
    int nq8 = Q >> 3;
    int q8 = blockIdx.x * 256 + threadIdx.x;
    if (q8 >= nq8) return;
    const uint4* base = (const uint4*)(cd + (size_t)n * P * Q) + q8;

    float ce[8];
    {
        uint4 u0 = *(const uint4*)(dmin + n * Q + q8 * 8);
        uint4 u1 = *(const uint4*)(dmin + n * Q + q8 * 8 + 4);
        ce[0] = (-2.0f * LOG2E) / (u2fl(u0.x) + EPSV);
        ce[1] = (-2.0f * LOG2E) / (u2fl(u0.y) + EPSV);
        ce[2] = (-2.0f * LOG2E) / (u2fl(u0.z) + EPSV);
        ce[3] = (-2.0f * LOG2E) / (u2fl(u0.w) + EPSV);
        ce[4] = (-2.0f * LOG2E) / (u2fl(u1.x) + EPSV);
        ce[5] = (-2.0f * LOG2E) / (u2fl(u1.y) + EPSV);
        ce[6] = (-2.0f * LOG2E) / (u2fl(u1.z) + EPSV);
        ce[7] = (-2.0f * LOG2E) / (u2fl(u1.w) + EPSV);
    }
    int r0 = sl * rps;
    float s[8];
    #pragma unroll
    for (int i = 0; i < 8; i++) s[i] = 0.f;
    #pragma unroll 4
    for (int r = r0; r < r0 + rps; r++) {
        uint4 v = base[(size_t)r * nq8];
        float2 f0 = __half22float2(*(__half2*)&v.x);
        float2 f1 = __half22float2(*(__half2*)&v.y);
        float2 f2 = __half22float2(*(__half2*)&v.z);
        float2 f3 = __half22float2(*(__half2*)&v.w);
        s[0] += exp2f(fmaf(ce[0], f0.x, K2C));
        s[1] += exp2f(fmaf(ce[1], f0.y, K2C));
        s[2] += exp2f(fmaf(ce[2], f1.x, K2C));
        s[3] += exp2f(fmaf(ce[3], f1.y, K2C));
        s[4] += exp2f(fmaf(ce[4], f2.x, K2C));
        s[5] += exp2f(fmaf(ce[5], f2.y, K2C));
        s[6] += exp2f(fmaf(ce[6], f3.x, K2C));
        s[7] += exp2f(fmaf(ce[7], f3.y, K2C));
    }
    float* pw = pout + ((size_t)n * nsl + sl) * Q + q8 * 8;
    *(float4*)pw       = make_float4(s[0], s[1], s[2], s[3]);
    *(float4*)(pw + 4) = make_float4(s[4], s[5], s[6], s[7]);
}

// ---------------- 5) stage2 sum -> be = 2log2e - log2(S) -------------------------
__global__ __launch_bounds__(256) void stage2_sum_k(
    const float* __restrict__ pin, float* __restrict__ be, int Q, int nsl)
{
    int n = blockIdx.y;
    int q = blockIdx.x * 256 + threadIdx.x;
    if (q >= Q) return;
    float s = 0.f;
    #pragma unroll 7
    for (int sl = 0; sl < nsl; sl++)
        s += pin[((size_t)n * nsl + sl) * Q + q];
    be[n * Q + q] = K2C - log2f(s);
}

// ---------------- 6) row max: rm_p = max_q (c0e_q*cd + be_q) ---------------------
__global__ __launch_bounds__(256) void rowmax_k(
    const __half* __restrict__ cd, const unsigned int* __restrict__ dmin,
    const float* __restrict__ be, float* __restrict__ rm, int P, int Q)
{
    __shared__ float sc[HW3], sb[HW3];
    int n = blockIdx.y;
    for (int i = threadIdx.x; i < Q; i += 256) {
        sc[i] = (-2.0f * LOG2E) / (u2fl(dmin[n * Q + i]) + EPSV);
        sb[i] = be[n * Q + i];
    }
    __syncthreads();
    int p = blockIdx.x * 8 + (threadIdx.x >> 5);
    int lane = threadIdx.x & 31;
    if (p >= P) return;
    const uint4* row = (const uint4*)(cd + (size_t)n * P * Q + (size_t)p * Q);
    int nq8 = Q >> 3;
    float m = -3.4e38f;
    for (int i = lane; i < nq8; i += 32) {
        uint4 v = row[i];
        int qb = i * 8;
        float2 f0 = __half22float2(*(__half2*)&v.x);
        float2 f1 = __half22float2(*(__half2*)&v.y);
        float2 f2 = __half22float2(*(__half2*)&v.z);
        float2 f3 = __half22float2(*(__half2*)&v.w);
        m = fmaxf(m, fmaf(sc[qb],     f0.x, sb[qb]));
        m = fmaxf(m, fmaf(sc[qb + 1], f0.y, sb[qb + 1]));
        m = fmaxf(m, fmaf(sc[qb + 2], f1.x, sb[qb + 2]));
        m = fmaxf(m, fmaf(sc[qb + 3], f1.y, sb[qb + 3]));
        m = fmaxf(m, fmaf(sc[qb + 4], f2.x, sb[qb + 4]));
        m = fmaxf(m, fmaf(sc[qb + 5], f2.y, sb[qb + 5]));
        m = fmaxf(m, fmaf(sc[qb + 6], f3.x, sb[qb + 6]));
        m = fmaxf(m, fmaf(sc[qb + 7], f3.y, sb[qb + 7]));
    }
    #pragma unroll
    for (int o = 16; o > 0; o >>= 1)
        m = fmaxf(m, __shfl_xor_sync(0xffffffffu, m, o));
    if (lane == 0) rm[n * P + p] = m;
}

// ---------------- 7) final -------------------------------------------------------
__global__ __launch_bounds__(256) void final_k(
    const float* __restrict__ rm3, const float* __restrict__ rm4,
    float* __restrict__ out)
{
    __shared__ float red[256];
    int tid = threadIdx.x;
    float total = 0.f;
    for (int n = 0; n < NB; n++) {
        float s = 0.f;
        for (int p = tid; p < HW3; p += 256) s += exp2f(rm3[n * HW3 + p]);
        red[tid] = s;
        __syncthreads();
        for (int o = 128; o > 0; o >>= 1) {
            if (tid < o) red[tid] += red[tid + o];
            __syncthreads();
        }
        total += 0.5f * (-logf(red[0] / (float)HW3));
        __syncthreads();
    }
    for (int n = 0; n < NB; n++) {
        float s = 0.f;
        for (int p = tid; p < HW4; p += 256) s += exp2f(rm4[n * HW4 + p]);
        red[tid] = s;
        __syncthreads();
        for (int o = 128; o > 0; o >>= 1) {
            if (tid < o) red[tid] += red[tid + o];
            __syncthreads();
        }
        total += 1.0f * (-logf(red[0] / (float)HW4));
        __syncthreads();
    }
    if (tid == 0) out[0] = total;
}

// ---------------- launch ---------------------------------------------------------
extern "C" void kernel_launch(void* const* d_in, const int* in_sizes, int n_in,
                              void* d_out, int out_size)
{
    const float* gen3 = (const float*)d_in[0];
    const float* tar3 = (const float*)d_in[1];
    const float* gen4 = (const float*)d_in[2];
    const float* tar4 = (const float*)d_in[3];

    __nv_bfloat16 *tT3, *gT3, *tT4, *gT4;
    __half *cd3, *cd4;
    float *mean, *rg, *rt, *pred, *be, *rm3, *rm4;
    unsigned int* dmin;
    cudaGetSymbolAddress((void**)&tT3, d_tT3);
    cudaGetSymbolAddress((void**)&gT3, d_gT3);
    cudaGetSymbolAddress((void**)&tT4, d_tT4);
    cudaGetSymbolAddress((void**)&gT4, d_gT4);
    cudaGetSymbolAddress((void**)&cd3, d_cd3);
    cudaGetSymbolAddress((void**)&cd4, d_cd4);
    cudaGetSymbolAddress((void**)&mean, d_mean);
    cudaGetSymbolAddress((void**)&rg, d_rg);
    cudaGetSymbolAddress((void**)&rt, d_rt);
    cudaGetSymbolAddress((void**)&dmin, d_dmin);
    cudaGetSymbolAddress((void**)&pred, d_pred);
    cudaGetSymbolAddress((void**)&be, d_be);
    cudaGetSymbolAddress((void**)&rm3, d_rm3);
    cudaGetSymbolAddress((void**)&rm4, d_rm4);

    cudaFuncSetAttribute(gemm_cd_mma, cudaFuncAttributeMaxDynamicSharedMemorySize, SMEMT);

    // ---- layer 3 ----
    stats_k<<<dim3(HW3 / 32, NB), 128>>>(gen3, tar3, mean, rg, rt, dmin, C3, HW3);
    trans_k<<<dim3(C3 / 32, HWP3 / 32, NB), 256>>>(gen3, tar3, mean, rg, rt, gT3, tT3, C3, HW3, HWP3);
    gemm_cd_mma<<<dim3(HWP3 / 128, HWP3 / 128, NB), 256, SMEMT>>>(
        tT3, gT3, cd3, dmin, C3, HW3, HW3, HWP3, HWP3);
    colsum_k<<<dim3(2, NSLS3, NB), 256>>>(cd3, dmin, pred, HW3, HW3, RPSS, NSLS3);
    stage2_sum_k<<<dim3((HW3 + 255) / 256, NB), 256>>>(pred, be, HW3, NSLS3);
    rowmax_k<<<dim3((HW3 + 7) / 8, NB), 256>>>(cd3, dmin, be, rm3, HW3, HW3);

    // ---- layer 4 ----
    stats_k<<<dim3((HW4 + 31) / 32, NB), 128>>>(gen4, tar4, mean, rg, rt, dmin, C4, HW4);
    trans_k<<<dim3(C4 / 32, HWP4 / 32, NB), 256>>>(gen4, tar4, mean, rg, rt, gT4, tT4, C4, HW4, HWP4);
    gemm_cd_mma<<<dim3(HWP4 / 128, HWP4 / 128, NB), 256, SMEMT>>>(
        tT4, gT4, cd4, dmin, C4, HW4, HW4, HWP4, HWP4);
    colsum_k<<<dim3(1, NSLS4, NB), 256>>>(cd4, dmin, pred, HW4, HW4, RPSS, NSLS4);
    stage2_sum_k<<<dim3((HW4 + 255) / 256, NB), 256>>>(pred, be, HW4, NSLS4);
    rowmax_k<<<dim3((HW4 + 7) / 8, NB), 256>>>(cd4, dmin, be, rm4, HW4, HW4);

    final_k<<<1, 256>>>(rm3, rm4, (float*)d_out);
}